// round 16
// baseline (speedup 1.0000x reference)
#include <cuda_runtime.h>
#include <cuda_bf16.h>
#include <math.h>

#define BATCH 8
#define HID 128
#define TFRAMES 800
#define LSAMP 192000
#define NB 24
#define LSCALE ((float)(800.0 / 192000.0))

typedef unsigned long long ull;

// ---- packed fp32x2 helpers ----
__device__ __forceinline__ ull pk2(float lo, float hi) {
    ull r; asm("mov.b64 %0, {%1, %2};" : "=l"(r) : "f"(lo), "f"(hi)); return r;
}
__device__ __forceinline__ ull dup2(float v) {
    ull r; asm("mov.b64 %0, {%1, %1};" : "=l"(r) : "f"(v)); return r;
}
__device__ __forceinline__ void fma2(ull& acc, ull a, ull b) {
    asm("fma.rn.f32x2 %0, %1, %2, %0;" : "+l"(acc) : "l"(a), "l"(b));
}
__device__ __forceinline__ float2 upk2(ull v) {
    float2 f; asm("mov.b64 {%0, %1}, %2;" : "=f"(f.x), "=f"(f.y) : "l"(v)); return f;
}

// ---------------- scratch ----------------
__device__ float g_h1[BATCH * 256 * TFRAMES];
__device__ float g_partA[2 * BATCH * 256 * TFRAMES];
__device__ float g_partB[2 * BATCH * 256 * TFRAMES];
__device__ float g_att[BATCH * TFRAMES];
__device__ float g_int[BATCH * TFRAMES];
__device__ float g_ssg[BATCH * HID * TFRAMES];
__device__ float g_wf[BATCH * TFRAMES * 32];
__device__ float g_nf[BATCH * TFRAMES * 64];
__device__ float g_filt[BATCH * LSAMP];
__device__ float g_wt1[128 * 3 * 256];
__device__ float g_wt2[256 * 3 * 256];
__device__ float g_wts[128 * 3 * 128];
__device__ float g_w3t[256 * 28];
__device__ float g_w2t[128 * 4];

// ---------------- weight prep, split ----------------
__global__ void prep_w1(const float* __restrict__ w1, float* __restrict__ wt1) {
    const int N1 = 256 * 128 * 3;
    for (int i = blockIdx.x * blockDim.x + threadIdx.x; i < N1; i += gridDim.x * blockDim.x) {
        int co = i / (128 * 3), rem = i - co * (128 * 3);
        wt1[rem * 256 + co] = w1[i];
    }
}

__global__ void prep_rest(const float* __restrict__ w2, const float* __restrict__ ws,
                          const float* __restrict__ w3, const float* __restrict__ wss2,
                          float* __restrict__ wt2, float* __restrict__ wts,
                          float* __restrict__ w3t, float* __restrict__ w2t) {
    const int N2 = 256 * 256 * 3, NS = 128 * 128 * 3, N3 = 256 * 28, N4 = 128 * 4;
    int total = N2 + NS + N3 + N4;
    for (int idx = blockIdx.x * blockDim.x + threadIdx.x; idx < total;
         idx += gridDim.x * blockDim.x) {
        int i = idx;
        if (i < N2) {
            int co = i / (256 * 3), rem = i - co * (256 * 3);
            wt2[rem * 256 + co] = w2[i];
        } else if ((i -= N2) < NS) {
            int co = i / (128 * 3), rem = i - co * (128 * 3);
            wts[rem * 128 + co] = ws[i];
        } else if ((i -= NS) < N3) {
            int ci = i / 28, co = i - ci * 28;
            w3t[i] = (co < 27) ? w3[co * 256 + ci] : 0.f;
        } else {
            i -= N3;
            int ci = i / 4, f = i - ci * 4;
            w2t[i] = wss2[f * 128 + ci];
        }
    }
}

// ---------------- K=3 conv, split-CIN partial GEMM (t-chunked via toff) ----------------
template <int CIN, int COUT>
__global__ void __launch_bounds__(256) conv3s(const float* __restrict__ x,
                                              const float* __restrict__ wt,
                                              float* __restrict__ part, int toff) {
    __shared__ __align__(16) float sx[32][68];
    __shared__ __align__(16) float swf[96 * 64];
    const int tid = threadIdx.x;
    const int cx = tid & 15, tx = tid >> 4;
    const int t_base = tx * 4, co_base = cx * 4;
    const int nstrips = COUT / 64;
    const int half = blockIdx.y / nstrips;
    const int c0 = (blockIdx.y - half * nstrips) * 64;
    const int b = blockIdx.z, t0 = (blockIdx.x + toff) * 64;
    const int ci_lo = half * (CIN / 2), ci_hi = ci_lo + CIN / 2;

    ull acc[2][4];
#pragma unroll
    for (int i = 0; i < 4; i++) { acc[0][i] = 0ull; acc[1][i] = 0ull; }

    for (int ci0 = ci_lo; ci0 < ci_hi; ci0 += 32) {
#pragma unroll 1
        for (int idx = tid; idx < 32 * 66; idx += 256) {
            int kc = idx / 66, i = idx - kc * 66;
            int t = t0 + i - 1;
            sx[kc][i] = (t >= 0 && t < TFRAMES)
                            ? x[((size_t)(b * CIN + ci0 + kc)) * TFRAMES + t] : 0.f;
        }
#pragma unroll 1
        for (int idx = tid; idx < 6144; idx += 256) {
            swf[idx] = wt[(size_t)(ci0 * 3 + (idx >> 6)) * COUT + c0 + (idx & 63)];
        }
        __syncthreads();
#pragma unroll 4
        for (int kc = 0; kc < 32; kc++) {
            const float* xr = &sx[kc][t_base];
            float4 xa = *(const float4*)xr;
            float2 xb = *(const float2*)(xr + 4);
            ull xd[6];
            xd[0] = dup2(xa.x); xd[1] = dup2(xa.y); xd[2] = dup2(xa.z);
            xd[3] = dup2(xa.w); xd[4] = dup2(xb.x); xd[5] = dup2(xb.y);
            ulonglong2 W0 = *(const ulonglong2*)&swf[kc * 192 + co_base];
            ulonglong2 W1 = *(const ulonglong2*)&swf[kc * 192 + 64 + co_base];
            ulonglong2 W2 = *(const ulonglong2*)&swf[kc * 192 + 128 + co_base];
            ull wa[2] = {W0.x, W0.y}, wb[2] = {W1.x, W1.y}, wc[2] = {W2.x, W2.y};
#pragma unroll
            for (int jp = 0; jp < 2; jp++) {
#pragma unroll
                for (int i = 0; i < 4; i++) {
                    fma2(acc[jp][i], wa[jp], xd[i]);
                    fma2(acc[jp][i], wb[jp], xd[i + 1]);
                    fma2(acc[jp][i], wc[jp], xd[i + 2]);
                }
            }
        }
        __syncthreads();
    }

    const int t_out = t0 + t_base;
    float* base = part + (size_t)half * BATCH * COUT * TFRAMES;
#pragma unroll
    for (int jp = 0; jp < 2; jp++) {
        float2 f0 = upk2(acc[jp][0]), f1 = upk2(acc[jp][1]);
        float2 f2 = upk2(acc[jp][2]), f3 = upk2(acc[jp][3]);
        float* yr0 = base + ((size_t)(b * COUT + c0 + co_base + jp * 2)) * TFRAMES + t_out;
        float* yr1 = yr0 + TFRAMES;
        if (t_out + 3 < TFRAMES) {
            *(float4*)yr0 = make_float4(f0.x, f1.x, f2.x, f3.x);
            *(float4*)yr1 = make_float4(f0.y, f1.y, f2.y, f3.y);
        } else {
            float vlo[4] = {f0.x, f1.x, f2.x, f3.x};
            float vhi[4] = {f0.y, f1.y, f2.y, f3.y};
#pragma unroll
            for (int i = 0; i < 4; i++)
                if (t_out + i < TFRAMES) { yr0[i] = vlo[i]; yr1[i] = vhi[i]; }
        }
    }
}

// ---------------- combine over a t-range ----------------
__global__ void __launch_bounds__(256) combine_range(const float* __restrict__ part,
                                                     const float* __restrict__ bias,
                                                     float* __restrict__ y,
                                                     int t_lo, int t_len) {
    const int per_row = t_len / 4;
    const int n4 = BATCH * 256 * per_row;
    int i4 = blockIdx.x * 256 + threadIdx.x;
    if (i4 >= n4) return;
    int row = i4 / per_row, off = i4 - row * per_row;
    size_t idx = (size_t)row * TFRAMES + t_lo + off * 4;
    const size_t npart = (size_t)BATCH * 256 * TFRAMES;
    float4 a = *(const float4*)(part + idx);
    float4 c = *(const float4*)(part + npart + idx);
    float bv = __ldg(&bias[row & 255]);
    float v0 = a.x + c.x + bv, v1 = a.y + c.y + bv;
    float v2 = a.z + c.z + bv, v3 = a.w + c.w + bv;
    float4 o;
    o.x = v0 > 0.f ? v0 : 0.1f * v0;
    o.y = v1 > 0.f ? v1 : 0.1f * v1;
    o.z = v2 > 0.f ? v2 : 0.1f * v2;
    o.w = v3 > 0.f ? v3 : 0.1f * v3;
    *(float4*)(y + idx) = o;
}

// ---------------- K=3 conv + bias + leaky_relu (side branch) ----------------
template <int CIN, int COUT>
__global__ void __launch_bounds__(256) conv3t(const float* __restrict__ x,
                                              const float* __restrict__ wt,
                                              const float* __restrict__ bias,
                                              float* __restrict__ y) {
    __shared__ __align__(16) float sx[32][68];
    __shared__ __align__(16) float swf[96 * 64];
    const int tid = threadIdx.x;
    const int cx = tid & 15, tx = tid >> 4;
    const int t_base = tx * 4, co_base = cx * 4;
    const int b = blockIdx.z, c0 = blockIdx.y * 64, t0 = blockIdx.x * 64;

    ull acc[2][4];
    {
        const float4 bv = *(const float4*)&bias[c0 + co_base];
        ull p0 = pk2(bv.x, bv.y), p1 = pk2(bv.z, bv.w);
#pragma unroll
        for (int i = 0; i < 4; i++) { acc[0][i] = p0; acc[1][i] = p1; }
    }

    for (int ci0 = 0; ci0 < CIN; ci0 += 32) {
#pragma unroll 1
        for (int idx = tid; idx < 32 * 66; idx += 256) {
            int kc = idx / 66, i = idx - kc * 66;
            int t = t0 + i - 1;
            sx[kc][i] = (t >= 0 && t < TFRAMES)
                            ? x[((size_t)(b * CIN + ci0 + kc)) * TFRAMES + t] : 0.f;
        }
#pragma unroll 1
        for (int idx = tid; idx < 6144; idx += 256) {
            swf[idx] = wt[(size_t)(ci0 * 3 + (idx >> 6)) * COUT + c0 + (idx & 63)];
        }
        __syncthreads();
#pragma unroll 4
        for (int kc = 0; kc < 32; kc++) {
            const float* xr = &sx[kc][t_base];
            float4 xa = *(const float4*)xr;
            float2 xb = *(const float2*)(xr + 4);
            ull xd[6];
            xd[0] = dup2(xa.x); xd[1] = dup2(xa.y); xd[2] = dup2(xa.z);
            xd[3] = dup2(xa.w); xd[4] = dup2(xb.x); xd[5] = dup2(xb.y);
            ulonglong2 W0 = *(const ulonglong2*)&swf[kc * 192 + co_base];
            ulonglong2 W1 = *(const ulonglong2*)&swf[kc * 192 + 64 + co_base];
            ulonglong2 W2 = *(const ulonglong2*)&swf[kc * 192 + 128 + co_base];
            ull wa[2] = {W0.x, W0.y}, wb[2] = {W1.x, W1.y}, wc[2] = {W2.x, W2.y};
#pragma unroll
            for (int jp = 0; jp < 2; jp++) {
#pragma unroll
                for (int i = 0; i < 4; i++) {
                    fma2(acc[jp][i], wa[jp], xd[i]);
                    fma2(acc[jp][i], wb[jp], xd[i + 1]);
                    fma2(acc[jp][i], wc[jp], xd[i + 2]);
                }
            }
        }
        __syncthreads();
    }

    const int t_out = t0 + t_base;
#pragma unroll
    for (int jp = 0; jp < 2; jp++) {
        float vlo[4], vhi[4];
#pragma unroll
        for (int i = 0; i < 4; i++) {
            float2 f = upk2(acc[jp][i]);
            vlo[i] = f.x > 0.f ? f.x : 0.1f * f.x;
            vhi[i] = f.y > 0.f ? f.y : 0.1f * f.y;
        }
        float* yr0 = y + ((size_t)(b * COUT + c0 + co_base + jp * 2)) * TFRAMES + t_out;
        float* yr1 = yr0 + TFRAMES;
        if (t_out + 3 < TFRAMES) {
            *(float4*)yr0 = make_float4(vlo[0], vlo[1], vlo[2], vlo[3]);
            *(float4*)yr1 = make_float4(vhi[0], vhi[1], vhi[2], vhi[3]);
        } else {
#pragma unroll
            for (int i = 0; i < 4; i++)
                if (t_out + i < TFRAMES) { yr0[i] = vlo[i]; yr1[i] = vhi[i]; }
        }
    }
}

// ---------------- noise-predictor head (fused combine2) + WF, t-chunked ----------------
__global__ void __launch_bounds__(256) np_head5(const float* __restrict__ part,
                                                const float* __restrict__ hbias,
                                                const float* __restrict__ w3t,
                                                const float* __restrict__ b3,
                                                const float* __restrict__ fbw,
                                                float* __restrict__ wf,
                                                float* __restrict__ att,
                                                float* __restrict__ inten, int xoff) {
    __shared__ __align__(16) float swh[256 * 28];
    __shared__ float swfb[24 * 31];
    __shared__ float sbias[256];
    __shared__ float sbd[64][25];
    const int tid = threadIdx.x;
    for (int idx = tid; idx < 256 * 28; idx += 256) {
        int ci = idx / 28, q = idx - ci * 28;
        int i = ci & 63, cg = ci >> 6;
        swh[(i * 4 + cg) * 28 + q] = w3t[idx];
    }
    for (int idx = tid; idx < 744; idx += 256) swfb[idx] = fbw[idx];
    sbias[tid] = hbias[tid];
    __syncthreads();

    const int lane = tid & 31, warp = tid >> 5;
    const int cg = lane >> 3, tsub = lane & 7;
    const int b = blockIdx.y;
    const int t0 = (blockIdx.x + xoff) * 64;
    const int lt = warp * 8 + tsub;
    const int t = t0 + lt;
    const int tc = min(t, TFRAMES - 1);

    ull acc[14];
#pragma unroll
    for (int q = 0; q < 14; q++) acc[q] = 0ull;

    const float* p0 = part + ((size_t)(b * 256 + cg * 64)) * TFRAMES + tc;
    const float* p1 = p0 + (size_t)BATCH * 256 * TFRAMES;
#pragma unroll 4
    for (int i = 0; i < 64; i++) {
        float a = __ldg(p0 + (size_t)i * TFRAMES) + __ldg(p1 + (size_t)i * TFRAMES) +
                  sbias[cg * 64 + i];
        a = a > 0.f ? a : 0.1f * a;
        ull xd = dup2(a);
        const ull* wr = (const ull*)&swh[(i * 4 + cg) * 28];
#pragma unroll
        for (int q = 0; q < 14; q++) fma2(acc[q], wr[q], xd);
    }

    float r[28];
#pragma unroll
    for (int q = 0; q < 14; q++) {
        float2 f = upk2(acc[q]);
        r[2 * q] = f.x; r[2 * q + 1] = f.y;
    }
#pragma unroll
    for (int q = 0; q < 28; q++) {
        r[q] += __shfl_xor_sync(0xffffffffu, r[q], 8);
        r[q] += __shfl_xor_sync(0xffffffffu, r[q], 16);
    }
    if (cg == 0 && t < TFRAMES) {
#pragma unroll
        for (int co = 0; co < NB; co++)
            sbd[lt][co] = 1.f / (1.f + expf(-(r[co] + b3[co])));
        att[b * TFRAMES + t] = 10.f / (1.f + expf(-(r[24] + b3[24])));
        inten[b * TFRAMES + t] = 1.f / (1.f + expf(-(r[26] + b3[26])));
    }
    __syncthreads();

    for (int idx = tid; idx < 64 * 32; idx += 256) {
        int l = idx >> 5, k = idx & 31;
        int tg = t0 + l;
        if (tg < TFRAMES) {
            float a = 0.f;
            if (k < 31) {
#pragma unroll
                for (int bd = 0; bd < NB; bd++) a += sbd[l][bd] * swfb[bd * 31 + k];
            }
            wf[((size_t)b * TFRAMES + tg) * 32 + k] = a;
        }
    }
}

// ---------------- spectral-shaper head: split-channel + NF blend ----------------
// warp: 4 channel-groups (32 ch) x 8 t; block 256 = 64 t; grid (13, BATCH)
__global__ void __launch_bounds__(256) ss_head4(const float* __restrict__ g,
                                                const float* __restrict__ w2t,
                                                const float* __restrict__ b2,
                                                const float* __restrict__ ntw_w,
                                                float* __restrict__ nfout) {
    __shared__ __align__(16) float sw[128 * 4];   // interleaved [(i*4+cg)*4+f]
    __shared__ float snt[252];
    __shared__ float sp[64][4];
    const int tid = threadIdx.x;
    for (int idx = tid; idx < 128 * 4; idx += 256) {
        int ci = idx >> 2, f = idx & 3;
        int i = ci & 31, cg = ci >> 5;
        sw[(i * 4 + cg) * 4 + f] = w2t[idx];
    }
    for (int i = tid; i < 252; i += 256) snt[i] = ntw_w[i];
    __syncthreads();

    const int lane = tid & 31, warp = tid >> 5;
    const int cg = lane >> 3, tsub = lane & 7;
    const int b = blockIdx.y;
    const int t0 = blockIdx.x * 64;
    const int lt = warp * 8 + tsub;
    const int t = t0 + lt;
    const int tc = min(t, TFRAMES - 1);

    ull a01 = 0ull, a23 = 0ull;
    const float* gb = g + ((size_t)(b * HID + cg * 32)) * TFRAMES + tc;
#pragma unroll 8
    for (int i = 0; i < 32; i++) {
        ull xd = dup2(__ldg(gb + (size_t)i * TFRAMES));
        const ull* wr = (const ull*)&sw[(i * 4 + cg) * 4];
        fma2(a01, wr[0], xd);
        fma2(a23, wr[1], xd);
    }
    float2 f01 = upk2(a01), f23 = upk2(a23);
    float r[4] = {f01.x, f01.y, f23.x, f23.y};
#pragma unroll
    for (int q = 0; q < 4; q++) {
        r[q] += __shfl_xor_sync(0xffffffffu, r[q], 8);
        r[q] += __shfl_xor_sync(0xffffffffu, r[q], 16);
    }
    if (cg == 0 && t < TFRAMES) {
        float v0 = r[0] + b2[0], v1 = r[1] + b2[1], v2 = r[2] + b2[2], v3 = r[3] + b2[3];
        float m = fmaxf(fmaxf(v0, v1), fmaxf(v2, v3));
        float e0 = expf(v0 - m), e1 = expf(v1 - m), e2 = expf(v2 - m), e3 = expf(v3 - m);
        float inv = 1.f / (e0 + e1 + e2 + e3);
        sp[lt][0] = e0 * inv; sp[lt][1] = e1 * inv;
        sp[lt][2] = e2 * inv; sp[lt][3] = e3 * inv;
    }
    __syncthreads();

    // cooperative NF write: nf[(b*T+t)*64 + k] (coalesced over k)
    for (int idx = tid; idx < 64 * 64; idx += 256) {
        int l = idx >> 6, k = idx & 63;
        int tg = t0 + l;
        if (tg < TFRAMES) {
            float v = 0.f;
            if (k < 63)
                v = sp[l][0] * snt[k] + sp[l][1] * snt[63 + k] +
                    sp[l][2] * snt[126 + k] + sp[l][3] * snt[189 + k];
            nfout[((size_t)b * TFRAMES + tg) * 64 + k] = v;
        }
    }
}

__device__ __forceinline__ float lin1s(const float* __restrict__ s, int j, int f0) {
    float pos = ((float)j + 0.5f) * LSCALE - 0.5f;
    pos = fminf(fmaxf(pos, 0.f), (float)(TFRAMES - 1));
    int i0 = (int)pos;
    int i1 = min(i0 + 1, TFRAMES - 1);
    float fw = pos - (float)i0;
    return s[i0 - f0] * (1.f - fw) + s[i1 - f0] * fw;
}

// ---------------- noise-type filtering via blended NF ----------------
#define MTILE 512
__global__ void __launch_bounds__(128) mix_noise3(const float* __restrict__ wn,
                                                  const float* __restrict__ nf,
                                                  float* __restrict__ filt) {
    __shared__ float sNF[6][64];
    __shared__ __align__(16) float sx[MTILE + 72];
    const int b = blockIdx.y;
    const int l0 = blockIdx.x * MTILE;
    const int tid = threadIdx.x;
    const int f0 = max(0, (int)floorf((l0 + 0.5f) * LSCALE - 0.5f));

    for (int i = tid; i < 6 * 64; i += 128) {
        int row = i >> 6, k = i & 63;
        sNF[row][k] = nf[((size_t)b * TFRAMES + min(f0 + row, TFRAMES - 1)) * 64 + k];
    }
    for (int i = tid; i < MTILE + 72; i += 128) {
        int l = l0 + i - 31;
        sx[i] = (l >= 0 && l < LSAMP) ? wn[(size_t)b * LSAMP + l] : 0.f;
    }
    __syncthreads();

    const int ts = tid * 4;
    int fA[4], fB[4];
    float w[4];
#pragma unroll
    for (int i = 0; i < 4; i++) {
        int l = l0 + ts + i;
        float pos = ((float)l + 0.5f) * LSCALE - 0.5f;
        pos = fminf(fmaxf(pos, 0.f), (float)(TFRAMES - 1));
        int i0 = (int)pos;
        int i1 = min(i0 + 1, TFRAMES - 1);
        w[i] = pos - (float)i0;
        fA[i] = i0 - f0;
        fB[i] = i1 - f0;
    }

    float acc0[4] = {0.f, 0.f, 0.f, 0.f};
    float acc1[4] = {0.f, 0.f, 0.f, 0.f};
    float xw[8];
    {
        float4 xa = *(const float4*)&sx[ts];
        float4 xb = *(const float4*)&sx[ts + 4];
        xw[0] = xa.x; xw[1] = xa.y; xw[2] = xa.z; xw[3] = xa.w;
        xw[4] = xb.x; xw[5] = xb.y; xw[6] = xb.z; xw[7] = xb.w;
    }
    if (fA[0] == fA[3]) {
        const float* rA = sNF[fA[0]];
        const float* rB = sNF[fB[0]];
#pragma unroll
        for (int c = 0; c < 16; c++) {
#pragma unroll
            for (int j = 0; j < 4; j++) {
                int k = c * 4 + j;
                float wa = rA[k], wb = rB[k];
#pragma unroll
                for (int i = 0; i < 4; i++) {
                    float xv = xw[j + i];
                    acc0[i] += xv * wa;
                    acc1[i] += xv * wb;
                }
            }
            if (c < 15) {
#pragma unroll
                for (int i = 0; i < 4; i++) xw[i] = xw[i + 4];
                float4 xn = *(const float4*)&sx[ts + c * 4 + 8];
                xw[4] = xn.x; xw[5] = xn.y; xw[6] = xn.z; xw[7] = xn.w;
            }
        }
    } else {
#pragma unroll 4
        for (int c = 0; c < 16; c++) {
#pragma unroll
            for (int j = 0; j < 4; j++) {
                int k = c * 4 + j;
#pragma unroll
                for (int i = 0; i < 4; i++) {
                    float xv = xw[j + i];
                    acc0[i] += xv * sNF[fA[i]][k];
                    acc1[i] += xv * sNF[fB[i]][k];
                }
            }
            if (c < 15) {
#pragma unroll
                for (int i = 0; i < 4; i++) xw[i] = xw[i + 4];
                float4 xn = *(const float4*)&sx[ts + c * 4 + 8];
                xw[4] = xn.x; xw[5] = xn.y; xw[6] = xn.z; xw[7] = xn.w;
            }
        }
    }
    float res[4];
#pragma unroll
    for (int i = 0; i < 4; i++) res[i] = acc0[i] * (1.f - w[i]) + acc1[i] * w[i];
    *(float4*)&filt[(size_t)b * LSAMP + l0 + ts] = make_float4(res[0], res[1], res[2], res[3]);
}

// ---------------- filter bank via blended WF + gate + outputs (l-chunked) ----------------
#define STILE 512
__global__ void __launch_bounds__(128) shape_out3(const float* __restrict__ filt,
                                                  const float* __restrict__ wf,
                                                  const float* __restrict__ attf,
                                                  const float* __restrict__ intf,
                                                  float* __restrict__ out, int write_gate,
                                                  int xoff) {
    __shared__ float sWF[6][32];
    __shared__ __align__(16) float sx[STILE + 40];
    __shared__ float sgr[STILE + 4];
    __shared__ float sia[16];
    const int b = blockIdx.y;
    const int l0 = (blockIdx.x + xoff) * STILE;
    const int tid = threadIdx.x;
    const int f0 = max(0, (int)floorf((l0 + 0.5f) * LSCALE - 0.5f));

    for (int i = tid; i < 6 * 32; i += 128) {
        int row = i >> 5, k = i & 31;
        sWF[row][k] = wf[((size_t)b * TFRAMES + min(f0 + row, TFRAMES - 1)) * 32 + k];
    }
    for (int i = tid; i < STILE + 40; i += 128) {
        int l = l0 + i - 15;
        sx[i] = (l >= 0 && l < LSAMP) ? filt[(size_t)b * LSAMP + l] : 0.f;
    }
    const int fg0 = max(0, (int)floorf((l0 - 2.5f) * LSCALE - 0.5f));
    if (tid < 16) {
        int fi = tid & 7;
        int fr = min(fg0 + fi, TFRAMES - 1);
        sia[tid] = (tid < 8) ? intf[b * TFRAMES + fr] : attf[b * TFRAMES + fr];
    }
    __syncthreads();

    for (int i = tid; i < STILE + 4; i += 128) {
        int j = l0 + i - 2;
        if (j < 0) j = -j;
        if (j > LSAMP - 1) j = 2 * (LSAMP - 1) - j;
        float il = lin1s(sia, j, fg0);
        float diff = (j == 0) ? 0.f : (il - lin1s(sia, j - 1, fg0));
        float gv = il;
        if (diff > 0.f) {
            float e = il;
            if (diff > 0.1f) e += lin1s(&sia[8], j, fg0) * 0.3f;
            gv = fminf(fmaxf(e, 0.f), 1.f);
        }
        sgr[i] = gv;
    }
    __syncthreads();

    const int ts = tid * 4;
    int fA[4], fB[4];
    float w[4];
#pragma unroll
    for (int i = 0; i < 4; i++) {
        int l = l0 + ts + i;
        float pos = ((float)l + 0.5f) * LSCALE - 0.5f;
        pos = fminf(fmaxf(pos, 0.f), (float)(TFRAMES - 1));
        int i0 = (int)pos;
        int i1 = min(i0 + 1, TFRAMES - 1);
        w[i] = pos - (float)i0;
        fA[i] = i0 - f0;
        fB[i] = i1 - f0;
    }

    float acc0[4] = {0.f, 0.f, 0.f, 0.f};
    float acc1[4] = {0.f, 0.f, 0.f, 0.f};
    float xw[8];
    {
        float4 xa = *(const float4*)&sx[ts];
        float4 xb = *(const float4*)&sx[ts + 4];
        xw[0] = xa.x; xw[1] = xa.y; xw[2] = xa.z; xw[3] = xa.w;
        xw[4] = xb.x; xw[5] = xb.y; xw[6] = xb.z; xw[7] = xb.w;
    }
    if (fA[0] == fA[3]) {
        const float* rA = sWF[fA[0]];
        const float* rB = sWF[fB[0]];
#pragma unroll
        for (int c = 0; c < 8; c++) {
#pragma unroll
            for (int j = 0; j < 4; j++) {
                int k = c * 4 + j;
                float wa = rA[k], wb = rB[k];
#pragma unroll
                for (int i = 0; i < 4; i++) {
                    float xv = xw[j + i];
                    acc0[i] += xv * wa;
                    acc1[i] += xv * wb;
                }
            }
            if (c < 7) {
#pragma unroll
                for (int i = 0; i < 4; i++) xw[i] = xw[i + 4];
                float4 xn = *(const float4*)&sx[ts + c * 4 + 8];
                xw[4] = xn.x; xw[5] = xn.y; xw[6] = xn.z; xw[7] = xn.w;
            }
        }
    } else {
#pragma unroll 4
        for (int c = 0; c < 8; c++) {
#pragma unroll
            for (int j = 0; j < 4; j++) {
                int k = c * 4 + j;
#pragma unroll
                for (int i = 0; i < 4; i++) {
                    float xv = xw[j + i];
                    acc0[i] += xv * sWF[fA[i]][k];
                    acc1[i] += xv * sWF[fB[i]][k];
                }
            }
            if (c < 7) {
#pragma unroll
                for (int i = 0; i < 4; i++) xw[i] = xw[i + 4];
                float4 xn = *(const float4*)&sx[ts + c * 4 + 8];
                xw[4] = xn.x; xw[5] = xn.y; xw[6] = xn.z; xw[7] = xn.w;
            }
        }
    }

    float shaped[4];
#pragma unroll
    for (int i = 0; i < 4; i++) shaped[i] = acc0[i] * (1.f - w[i]) + acc1[i] * w[i];

    float s[8];
#pragma unroll
    for (int ii = 0; ii < 8; ii++) s[ii] = sgr[ts + ii];
    float gv0 = 0.2f * (s[0] + s[1] + s[2] + s[3] + s[4]);
    float gv1 = 0.2f * (s[1] + s[2] + s[3] + s[4] + s[5]);
    float gv2 = 0.2f * (s[2] + s[3] + s[4] + s[5] + s[6]);
    float gv3 = 0.2f * (s[3] + s[4] + s[5] + s[6] + s[7]);
    *(float4*)&out[(size_t)b * LSAMP + l0 + ts] =
        make_float4(shaped[0] * gv0, shaped[1] * gv1, shaped[2] * gv2, shaped[3] * gv3);
    if (write_gate)
        *(float4*)&out[(size_t)BATCH * LSAMP + (size_t)b * LSAMP + l0 + ts] =
            make_float4(gv0, gv1, gv2, gv3);
}

// ---------------- launch ----------------
#define SHP_A 168

extern "C" void kernel_launch(void* const* d_in, const int* in_sizes, int n_in,
                              void* d_out, int out_size) {
    const float* cond  = (const float*)d_in[0];
    const float* wn    = (const float*)d_in[1];
    const float* np_w1 = (const float*)d_in[2];
    const float* np_b1 = (const float*)d_in[3];
    const float* np_w2 = (const float*)d_in[4];
    const float* np_b2 = (const float*)d_in[5];
    const float* np_w3 = (const float*)d_in[6];
    const float* np_b3 = (const float*)d_in[7];
    const float* ss_w1 = (const float*)d_in[8];
    const float* ss_b1 = (const float*)d_in[9];
    const float* ss_w2 = (const float*)d_in[10];
    const float* ss_b2 = (const float*)d_in[11];
    const float* fb_w  = (const float*)d_in[12];
    const float* nt_w  = (const float*)d_in[13];
    float* out = (float*)d_out;

    void *p_h1, *p_pA, *p_pB, *p_att, *p_int, *p_ssg, *p_wf, *p_nf, *p_filt;
    void *p_wt1, *p_wt2, *p_wts, *p_w3t, *p_w2t;
    cudaGetSymbolAddress(&p_h1, g_h1);
    cudaGetSymbolAddress(&p_pA, g_partA);
    cudaGetSymbolAddress(&p_pB, g_partB);
    cudaGetSymbolAddress(&p_att, g_att);
    cudaGetSymbolAddress(&p_int, g_int);
    cudaGetSymbolAddress(&p_ssg, g_ssg);
    cudaGetSymbolAddress(&p_wf, g_wf);
    cudaGetSymbolAddress(&p_nf, g_nf);
    cudaGetSymbolAddress(&p_filt, g_filt);
    cudaGetSymbolAddress(&p_wt1, g_wt1);
    cudaGetSymbolAddress(&p_wt2, g_wt2);
    cudaGetSymbolAddress(&p_wts, g_wts);
    cudaGetSymbolAddress(&p_w3t, g_w3t);
    cudaGetSymbolAddress(&p_w2t, g_w2t);

    static cudaStream_t s2 = nullptr, s3 = nullptr;
    static cudaEvent_t ev_fork = nullptr, ev_w1 = nullptr, ev_rest = nullptr,
                       ev_join = nullptr, ev_cbA = nullptr, ev_done3 = nullptr;
    if (s2 == nullptr) {
        cudaStreamCreateWithFlags(&s2, cudaStreamNonBlocking);
        cudaStreamCreateWithFlags(&s3, cudaStreamNonBlocking);
        cudaEventCreateWithFlags(&ev_fork, cudaEventDisableTiming);
        cudaEventCreateWithFlags(&ev_w1, cudaEventDisableTiming);
        cudaEventCreateWithFlags(&ev_rest, cudaEventDisableTiming);
        cudaEventCreateWithFlags(&ev_join, cudaEventDisableTiming);
        cudaEventCreateWithFlags(&ev_cbA, cudaEventDisableTiming);
        cudaEventCreateWithFlags(&ev_done3, cudaEventDisableTiming);
    }

    int write_gate = (out_size >= 2 * BATCH * LSAMP) ? 1 : 0;

    // fork side streams from origin stream first (graph-capture requirement)
    cudaEventRecord(ev_fork, 0);
    cudaStreamWaitEvent(s2, ev_fork, 0);
    cudaStreamWaitEvent(s3, ev_fork, 0);

    prep_w1<<<96, 256>>>(np_w1, (float*)p_wt1);
    cudaEventRecord(ev_w1, 0);
    prep_rest<<<212, 256, 0, s2>>>(np_w2, ss_w1, np_w3, ss_w2,
                                   (float*)p_wt2, (float*)p_wts, (float*)p_w3t, (float*)p_w2t);
    cudaEventRecord(ev_rest, s2);

    // side branch (s2)
    conv3t<128, 128><<<dim3(13, 2, BATCH), 256, 0, s2>>>(cond, (const float*)p_wts, ss_b1,
                                                          (float*)p_ssg);
    ss_head4<<<dim3(13, BATCH), 256, 0, s2>>>((const float*)p_ssg, (const float*)p_w2t,
                                              ss_b2, nt_w, (float*)p_nf);
    mix_noise3<<<dim3(LSAMP / MTILE, BATCH), 128, 0, s2>>>(wn, (const float*)p_nf,
                                                           (float*)p_filt);
    cudaEventRecord(ev_join, s2);

    // main chunk A (s0)
    conv3s<128, 256><<<dim3(7, 8, BATCH), 256>>>(cond, (const float*)p_wt1, (float*)p_pA, 0);
    combine_range<<<(BATCH * 256 * (448 / 4) + 255) / 256, 256>>>(
        (const float*)p_pA, np_b1, (float*)p_h1, 0, 448);
    cudaEventRecord(ev_cbA, 0);
    cudaStreamWaitEvent(0, ev_rest, 0);
    conv3s<256, 256><<<dim3(6, 8, BATCH), 256>>>((const float*)p_h1, (const float*)p_wt2,
                                                 (float*)p_pB, 0);
    np_head5<<<dim3(6, BATCH), 256>>>((const float*)p_pB, np_b2, (const float*)p_w3t, np_b3,
                                      fb_w, (float*)p_wf, (float*)p_att, (float*)p_int, 0);
    cudaStreamWaitEvent(0, ev_join, 0);
    shape_out3<<<dim3(SHP_A, BATCH), 128>>>((const float*)p_filt, (const float*)p_wf,
                                            (const float*)p_att, (const float*)p_int,
                                            out, write_gate, 0);

    // main chunk B (s3)
    cudaStreamWaitEvent(s3, ev_w1, 0);
    conv3s<128, 256><<<dim3(6, 8, BATCH), 256, 0, s3>>>(cond, (const float*)p_wt1,
                                                        (float*)p_pA, 7);
    combine_range<<<(BATCH * 256 * (352 / 4) + 255) / 256, 256, 0, s3>>>(
        (const float*)p_pA, np_b1, (float*)p_h1, 448, 352);
    cudaStreamWaitEvent(s3, ev_cbA, 0);
    cudaStreamWaitEvent(s3, ev_rest, 0);
    conv3s<256, 256><<<dim3(7, 8, BATCH), 256, 0, s3>>>((const float*)p_h1,
                                                        (const float*)p_wt2, (float*)p_pB, 6);
    np_head5<<<dim3(7, BATCH), 256, 0, s3>>>((const float*)p_pB, np_b2, (const float*)p_w3t,
                                             np_b3, fb_w, (float*)p_wf, (float*)p_att,
                                             (float*)p_int, 6);
    cudaStreamWaitEvent(s3, ev_join, 0);
    shape_out3<<<dim3(LSAMP / STILE - SHP_A, BATCH), 128, 0, s3>>>(
        (const float*)p_filt, (const float*)p_wf, (const float*)p_att, (const float*)p_int,
        out, write_gate, SHP_A);
    cudaEventRecord(ev_done3, s3);

    cudaStreamWaitEvent(0, ev_done3, 0);
}

// round 17
// speedup vs baseline: 1.0841x; 1.0841x over previous
#include <cuda_runtime.h>
#include <cuda_bf16.h>
#include <math.h>

#define BATCH 8
#define HID 128
#define TFRAMES 800
#define LSAMP 192000
#define NB 24
#define LSCALE ((float)(800.0 / 192000.0))

typedef unsigned long long ull;

// ---- packed fp32x2 helpers ----
__device__ __forceinline__ ull pk2(float lo, float hi) {
    ull r; asm("mov.b64 %0, {%1, %2};" : "=l"(r) : "f"(lo), "f"(hi)); return r;
}
__device__ __forceinline__ ull dup2(float v) {
    ull r; asm("mov.b64 %0, {%1, %1};" : "=l"(r) : "f"(v)); return r;
}
__device__ __forceinline__ void fma2(ull& acc, ull a, ull b) {
    asm("fma.rn.f32x2 %0, %1, %2, %0;" : "+l"(acc) : "l"(a), "l"(b));
}
__device__ __forceinline__ float2 upk2(ull v) {
    float2 f; asm("mov.b64 {%0, %1}, %2;" : "=f"(f.x), "=f"(f.y) : "l"(v)); return f;
}

// ---------------- scratch ----------------
__device__ float g_h1[BATCH * 256 * TFRAMES];
__device__ float g_partA[2 * BATCH * 256 * TFRAMES];
__device__ float g_partB[2 * BATCH * 256 * TFRAMES];
__device__ float g_att[BATCH * TFRAMES];
__device__ float g_int[BATCH * TFRAMES];
__device__ float g_ssg[BATCH * HID * TFRAMES];
__device__ float g_wf[BATCH * TFRAMES * 32];
__device__ float g_nf[BATCH * TFRAMES * 64];
__device__ float g_filt[BATCH * LSAMP];
__device__ float g_wt1[128 * 3 * 256];
__device__ float g_wt2[256 * 3 * 256];
__device__ float g_wts[128 * 3 * 128];
__device__ float g_w3t[256 * 28];
__device__ float g_w2t[128 * 4];

// ---------------- weight prep, split ----------------
__global__ void prep_w1(const float* __restrict__ w1, float* __restrict__ wt1) {
    const int N1 = 256 * 128 * 3;
    for (int i = blockIdx.x * blockDim.x + threadIdx.x; i < N1; i += gridDim.x * blockDim.x) {
        int co = i / (128 * 3), rem = i - co * (128 * 3);
        wt1[rem * 256 + co] = w1[i];
    }
}

__global__ void prep_rest(const float* __restrict__ w2, const float* __restrict__ ws,
                          const float* __restrict__ w3, const float* __restrict__ wss2,
                          float* __restrict__ wt2, float* __restrict__ wts,
                          float* __restrict__ w3t, float* __restrict__ w2t) {
    const int N2 = 256 * 256 * 3, NS = 128 * 128 * 3, N3 = 256 * 28, N4 = 128 * 4;
    int total = N2 + NS + N3 + N4;
    for (int idx = blockIdx.x * blockDim.x + threadIdx.x; idx < total;
         idx += gridDim.x * blockDim.x) {
        int i = idx;
        if (i < N2) {
            int co = i / (256 * 3), rem = i - co * (256 * 3);
            wt2[rem * 256 + co] = w2[i];
        } else if ((i -= N2) < NS) {
            int co = i / (128 * 3), rem = i - co * (128 * 3);
            wts[rem * 128 + co] = ws[i];
        } else if ((i -= NS) < N3) {
            int ci = i / 28, co = i - ci * 28;
            w3t[i] = (co < 27) ? w3[co * 256 + ci] : 0.f;
        } else {
            i -= N3;
            int ci = i / 4, f = i - ci * 4;
            w2t[i] = wss2[f * 128 + ci];
        }
    }
}

// ---------------- K=3 conv, split-CIN partial GEMM (t-chunked via toff) ----------------
// warp map: tx = tid&15 (16 t-groups), cx = tid>>4 (cout-group) -> weights warp-broadcast
template <int CIN, int COUT>
__global__ void __launch_bounds__(256) conv3s(const float* __restrict__ x,
                                              const float* __restrict__ wt,
                                              float* __restrict__ part, int toff) {
    __shared__ __align__(16) float sx[32][68];
    __shared__ __align__(16) float swf[96 * 64];
    const int tid = threadIdx.x;
    const int tx = tid & 15, cx = tid >> 4;
    const int t_base = tx * 4, co_base = cx * 4;
    const int nstrips = COUT / 64;
    const int half = blockIdx.y / nstrips;
    const int c0 = (blockIdx.y - half * nstrips) * 64;
    const int b = blockIdx.z, t0 = (blockIdx.x + toff) * 64;
    const int ci_lo = half * (CIN / 2), ci_hi = ci_lo + CIN / 2;

    ull acc[2][4];
#pragma unroll
    for (int i = 0; i < 4; i++) { acc[0][i] = 0ull; acc[1][i] = 0ull; }

    for (int ci0 = ci_lo; ci0 < ci_hi; ci0 += 32) {
#pragma unroll 1
        for (int idx = tid; idx < 32 * 66; idx += 256) {
            int kc = idx / 66, i = idx - kc * 66;
            int t = t0 + i - 1;
            sx[kc][i] = (t >= 0 && t < TFRAMES)
                            ? x[((size_t)(b * CIN + ci0 + kc)) * TFRAMES + t] : 0.f;
        }
#pragma unroll 1
        for (int idx = tid; idx < 6144; idx += 256) {
            swf[idx] = wt[(size_t)(ci0 * 3 + (idx >> 6)) * COUT + c0 + (idx & 63)];
        }
        __syncthreads();
#pragma unroll 4
        for (int kc = 0; kc < 32; kc++) {
            const float* xr = &sx[kc][t_base];
            float4 xa = *(const float4*)xr;
            float2 xb = *(const float2*)(xr + 4);
            ull xd[6];
            xd[0] = dup2(xa.x); xd[1] = dup2(xa.y); xd[2] = dup2(xa.z);
            xd[3] = dup2(xa.w); xd[4] = dup2(xb.x); xd[5] = dup2(xb.y);
            ulonglong2 W0 = *(const ulonglong2*)&swf[kc * 192 + co_base];
            ulonglong2 W1 = *(const ulonglong2*)&swf[kc * 192 + 64 + co_base];
            ulonglong2 W2 = *(const ulonglong2*)&swf[kc * 192 + 128 + co_base];
            ull wa[2] = {W0.x, W0.y}, wb[2] = {W1.x, W1.y}, wc[2] = {W2.x, W2.y};
#pragma unroll
            for (int jp = 0; jp < 2; jp++) {
#pragma unroll
                for (int i = 0; i < 4; i++) {
                    fma2(acc[jp][i], wa[jp], xd[i]);
                    fma2(acc[jp][i], wb[jp], xd[i + 1]);
                    fma2(acc[jp][i], wc[jp], xd[i + 2]);
                }
            }
        }
        __syncthreads();
    }

    const int t_out = t0 + t_base;
    float* base = part + (size_t)half * BATCH * COUT * TFRAMES;
#pragma unroll
    for (int jp = 0; jp < 2; jp++) {
        float2 f0 = upk2(acc[jp][0]), f1 = upk2(acc[jp][1]);
        float2 f2 = upk2(acc[jp][2]), f3 = upk2(acc[jp][3]);
        float* yr0 = base + ((size_t)(b * COUT + c0 + co_base + jp * 2)) * TFRAMES + t_out;
        float* yr1 = yr0 + TFRAMES;
        if (t_out + 3 < TFRAMES) {
            *(float4*)yr0 = make_float4(f0.x, f1.x, f2.x, f3.x);
            *(float4*)yr1 = make_float4(f0.y, f1.y, f2.y, f3.y);
        } else {
            float vlo[4] = {f0.x, f1.x, f2.x, f3.x};
            float vhi[4] = {f0.y, f1.y, f2.y, f3.y};
#pragma unroll
            for (int i = 0; i < 4; i++)
                if (t_out + i < TFRAMES) { yr0[i] = vlo[i]; yr1[i] = vhi[i]; }
        }
    }
}

// ---------------- combine over a t-range ----------------
__global__ void __launch_bounds__(256) combine_range(const float* __restrict__ part,
                                                     const float* __restrict__ bias,
                                                     float* __restrict__ y,
                                                     int t_lo, int t_len) {
    const int per_row = t_len / 4;
    const int n4 = BATCH * 256 * per_row;
    int i4 = blockIdx.x * 256 + threadIdx.x;
    if (i4 >= n4) return;
    int row = i4 / per_row, off = i4 - row * per_row;
    size_t idx = (size_t)row * TFRAMES + t_lo + off * 4;
    const size_t npart = (size_t)BATCH * 256 * TFRAMES;
    float4 a = *(const float4*)(part + idx);
    float4 c = *(const float4*)(part + npart + idx);
    float bv = __ldg(&bias[row & 255]);
    float v0 = a.x + c.x + bv, v1 = a.y + c.y + bv;
    float v2 = a.z + c.z + bv, v3 = a.w + c.w + bv;
    float4 o;
    o.x = v0 > 0.f ? v0 : 0.1f * v0;
    o.y = v1 > 0.f ? v1 : 0.1f * v1;
    o.z = v2 > 0.f ? v2 : 0.1f * v2;
    o.w = v3 > 0.f ? v3 : 0.1f * v3;
    *(float4*)(y + idx) = o;
}

// ---------------- K=3 conv + bias + leaky_relu (side branch) ----------------
template <int CIN, int COUT>
__global__ void __launch_bounds__(256) conv3t(const float* __restrict__ x,
                                              const float* __restrict__ wt,
                                              const float* __restrict__ bias,
                                              float* __restrict__ y) {
    __shared__ __align__(16) float sx[32][68];
    __shared__ __align__(16) float swf[96 * 64];
    const int tid = threadIdx.x;
    const int tx = tid & 15, cx = tid >> 4;
    const int t_base = tx * 4, co_base = cx * 4;
    const int b = blockIdx.z, c0 = blockIdx.y * 64, t0 = blockIdx.x * 64;

    ull acc[2][4];
    {
        const float4 bv = *(const float4*)&bias[c0 + co_base];
        ull p0 = pk2(bv.x, bv.y), p1 = pk2(bv.z, bv.w);
#pragma unroll
        for (int i = 0; i < 4; i++) { acc[0][i] = p0; acc[1][i] = p1; }
    }

    for (int ci0 = 0; ci0 < CIN; ci0 += 32) {
#pragma unroll 1
        for (int idx = tid; idx < 32 * 66; idx += 256) {
            int kc = idx / 66, i = idx - kc * 66;
            int t = t0 + i - 1;
            sx[kc][i] = (t >= 0 && t < TFRAMES)
                            ? x[((size_t)(b * CIN + ci0 + kc)) * TFRAMES + t] : 0.f;
        }
#pragma unroll 1
        for (int idx = tid; idx < 6144; idx += 256) {
            swf[idx] = wt[(size_t)(ci0 * 3 + (idx >> 6)) * COUT + c0 + (idx & 63)];
        }
        __syncthreads();
#pragma unroll 4
        for (int kc = 0; kc < 32; kc++) {
            const float* xr = &sx[kc][t_base];
            float4 xa = *(const float4*)xr;
            float2 xb = *(const float2*)(xr + 4);
            ull xd[6];
            xd[0] = dup2(xa.x); xd[1] = dup2(xa.y); xd[2] = dup2(xa.z);
            xd[3] = dup2(xa.w); xd[4] = dup2(xb.x); xd[5] = dup2(xb.y);
            ulonglong2 W0 = *(const ulonglong2*)&swf[kc * 192 + co_base];
            ulonglong2 W1 = *(const ulonglong2*)&swf[kc * 192 + 64 + co_base];
            ulonglong2 W2 = *(const ulonglong2*)&swf[kc * 192 + 128 + co_base];
            ull wa[2] = {W0.x, W0.y}, wb[2] = {W1.x, W1.y}, wc[2] = {W2.x, W2.y};
#pragma unroll
            for (int jp = 0; jp < 2; jp++) {
#pragma unroll
                for (int i = 0; i < 4; i++) {
                    fma2(acc[jp][i], wa[jp], xd[i]);
                    fma2(acc[jp][i], wb[jp], xd[i + 1]);
                    fma2(acc[jp][i], wc[jp], xd[i + 2]);
                }
            }
        }
        __syncthreads();
    }

    const int t_out = t0 + t_base;
#pragma unroll
    for (int jp = 0; jp < 2; jp++) {
        float vlo[4], vhi[4];
#pragma unroll
        for (int i = 0; i < 4; i++) {
            float2 f = upk2(acc[jp][i]);
            vlo[i] = f.x > 0.f ? f.x : 0.1f * f.x;
            vhi[i] = f.y > 0.f ? f.y : 0.1f * f.y;
        }
        float* yr0 = y + ((size_t)(b * COUT + c0 + co_base + jp * 2)) * TFRAMES + t_out;
        float* yr1 = yr0 + TFRAMES;
        if (t_out + 3 < TFRAMES) {
            *(float4*)yr0 = make_float4(vlo[0], vlo[1], vlo[2], vlo[3]);
            *(float4*)yr1 = make_float4(vhi[0], vhi[1], vhi[2], vhi[3]);
        } else {
#pragma unroll
            for (int i = 0; i < 4; i++)
                if (t_out + i < TFRAMES) { yr0[i] = vlo[i]; yr1[i] = vhi[i]; }
        }
    }
}

// ---------------- noise-predictor head (fused combine2) + WF, t-chunked ----------------
__global__ void __launch_bounds__(256) np_head5(const float* __restrict__ part,
                                                const float* __restrict__ hbias,
                                                const float* __restrict__ w3t,
                                                const float* __restrict__ b3,
                                                const float* __restrict__ fbw,
                                                float* __restrict__ wf,
                                                float* __restrict__ att,
                                                float* __restrict__ inten, int xoff) {
    __shared__ __align__(16) float swh[256 * 28];
    __shared__ float swfb[24 * 31];
    __shared__ float sbias[256];
    __shared__ float sbd[64][25];
    const int tid = threadIdx.x;
    for (int idx = tid; idx < 256 * 28; idx += 256) {
        int ci = idx / 28, q = idx - ci * 28;
        int i = ci & 63, cg = ci >> 6;
        swh[(i * 4 + cg) * 28 + q] = w3t[idx];
    }
    for (int idx = tid; idx < 744; idx += 256) swfb[idx] = fbw[idx];
    sbias[tid] = hbias[tid];
    __syncthreads();

    const int lane = tid & 31, warp = tid >> 5;
    const int cg = lane >> 3, tsub = lane & 7;
    const int b = blockIdx.y;
    const int t0 = (blockIdx.x + xoff) * 64;
    const int lt = warp * 8 + tsub;
    const int t = t0 + lt;
    const int tc = min(t, TFRAMES - 1);

    ull acc[14];
#pragma unroll
    for (int q = 0; q < 14; q++) acc[q] = 0ull;

    const float* p0 = part + ((size_t)(b * 256 + cg * 64)) * TFRAMES + tc;
    const float* p1 = p0 + (size_t)BATCH * 256 * TFRAMES;
#pragma unroll 4
    for (int i = 0; i < 64; i++) {
        float a = __ldg(p0 + (size_t)i * TFRAMES) + __ldg(p1 + (size_t)i * TFRAMES) +
                  sbias[cg * 64 + i];
        a = a > 0.f ? a : 0.1f * a;
        ull xd = dup2(a);
        const ull* wr = (const ull*)&swh[(i * 4 + cg) * 28];
#pragma unroll
        for (int q = 0; q < 14; q++) fma2(acc[q], wr[q], xd);
    }

    float r[28];
#pragma unroll
    for (int q = 0; q < 14; q++) {
        float2 f = upk2(acc[q]);
        r[2 * q] = f.x; r[2 * q + 1] = f.y;
    }
#pragma unroll
    for (int q = 0; q < 28; q++) {
        r[q] += __shfl_xor_sync(0xffffffffu, r[q], 8);
        r[q] += __shfl_xor_sync(0xffffffffu, r[q], 16);
    }
    if (cg == 0 && t < TFRAMES) {
#pragma unroll
        for (int co = 0; co < NB; co++)
            sbd[lt][co] = 1.f / (1.f + expf(-(r[co] + b3[co])));
        att[b * TFRAMES + t] = 10.f / (1.f + expf(-(r[24] + b3[24])));
        inten[b * TFRAMES + t] = 1.f / (1.f + expf(-(r[26] + b3[26])));
    }
    __syncthreads();

    for (int idx = tid; idx < 64 * 32; idx += 256) {
        int l = idx >> 5, k = idx & 31;
        int tg = t0 + l;
        if (tg < TFRAMES) {
            float a = 0.f;
            if (k < 31) {
#pragma unroll
                for (int bd = 0; bd < NB; bd++) a += sbd[l][bd] * swfb[bd * 31 + k];
            }
            wf[((size_t)b * TFRAMES + tg) * 32 + k] = a;
        }
    }
}

// ---------------- spectral-shaper head: split-channel + NF blend ----------------
__global__ void __launch_bounds__(256) ss_head4(const float* __restrict__ g,
                                                const float* __restrict__ w2t,
                                                const float* __restrict__ b2,
                                                const float* __restrict__ ntw_w,
                                                float* __restrict__ nfout) {
    __shared__ __align__(16) float sw[128 * 4];
    __shared__ float snt[252];
    __shared__ float sp[64][4];
    const int tid = threadIdx.x;
    for (int idx = tid; idx < 128 * 4; idx += 256) {
        int ci = idx >> 2, f = idx & 3;
        int i = ci & 31, cg = ci >> 5;
        sw[(i * 4 + cg) * 4 + f] = w2t[idx];
    }
    for (int i = tid; i < 252; i += 256) snt[i] = ntw_w[i];
    __syncthreads();

    const int lane = tid & 31, warp = tid >> 5;
    const int cg = lane >> 3, tsub = lane & 7;
    const int b = blockIdx.y;
    const int t0 = blockIdx.x * 64;
    const int lt = warp * 8 + tsub;
    const int t = t0 + lt;
    const int tc = min(t, TFRAMES - 1);

    ull a01 = 0ull, a23 = 0ull;
    const float* gb = g + ((size_t)(b * HID + cg * 32)) * TFRAMES + tc;
#pragma unroll 8
    for (int i = 0; i < 32; i++) {
        ull xd = dup2(__ldg(gb + (size_t)i * TFRAMES));
        const ull* wr = (const ull*)&sw[(i * 4 + cg) * 4];
        fma2(a01, wr[0], xd);
        fma2(a23, wr[1], xd);
    }
    float2 f01 = upk2(a01), f23 = upk2(a23);
    float r[4] = {f01.x, f01.y, f23.x, f23.y};
#pragma unroll
    for (int q = 0; q < 4; q++) {
        r[q] += __shfl_xor_sync(0xffffffffu, r[q], 8);
        r[q] += __shfl_xor_sync(0xffffffffu, r[q], 16);
    }
    if (cg == 0 && t < TFRAMES) {
        float v0 = r[0] + b2[0], v1 = r[1] + b2[1], v2 = r[2] + b2[2], v3 = r[3] + b2[3];
        float m = fmaxf(fmaxf(v0, v1), fmaxf(v2, v3));
        float e0 = expf(v0 - m), e1 = expf(v1 - m), e2 = expf(v2 - m), e3 = expf(v3 - m);
        float inv = 1.f / (e0 + e1 + e2 + e3);
        sp[lt][0] = e0 * inv; sp[lt][1] = e1 * inv;
        sp[lt][2] = e2 * inv; sp[lt][3] = e3 * inv;
    }
    __syncthreads();

    for (int idx = tid; idx < 64 * 64; idx += 256) {
        int l = idx >> 6, k = idx & 63;
        int tg = t0 + l;
        if (tg < TFRAMES) {
            float v = 0.f;
            if (k < 63)
                v = sp[l][0] * snt[k] + sp[l][1] * snt[63 + k] +
                    sp[l][2] * snt[126 + k] + sp[l][3] * snt[189 + k];
            nfout[((size_t)b * TFRAMES + tg) * 64 + k] = v;
        }
    }
}

__device__ __forceinline__ float lin1s(const float* __restrict__ s, int j, int f0) {
    float pos = ((float)j + 0.5f) * LSCALE - 0.5f;
    pos = fminf(fmaxf(pos, 0.f), (float)(TFRAMES - 1));
    int i0 = (int)pos;
    int i1 = min(i0 + 1, TFRAMES - 1);
    float fw = pos - (float)i0;
    return s[i0 - f0] * (1.f - fw) + s[i1 - f0] * fw;
}

// ---------------- noise-type filtering via blended NF ----------------
#define MTILE 512
__global__ void __launch_bounds__(128) mix_noise3(const float* __restrict__ wn,
                                                  const float* __restrict__ nf,
                                                  float* __restrict__ filt) {
    __shared__ float sNF[6][64];
    __shared__ __align__(16) float sx[MTILE + 72];
    const int b = blockIdx.y;
    const int l0 = blockIdx.x * MTILE;
    const int tid = threadIdx.x;
    const int f0 = max(0, (int)floorf((l0 + 0.5f) * LSCALE - 0.5f));

    for (int i = tid; i < 6 * 64; i += 128) {
        int row = i >> 6, k = i & 63;
        sNF[row][k] = nf[((size_t)b * TFRAMES + min(f0 + row, TFRAMES - 1)) * 64 + k];
    }
    for (int i = tid; i < MTILE + 72; i += 128) {
        int l = l0 + i - 31;
        sx[i] = (l >= 0 && l < LSAMP) ? wn[(size_t)b * LSAMP + l] : 0.f;
    }
    __syncthreads();

    const int ts = tid * 4;
    int fA[4], fB[4];
    float w[4];
#pragma unroll
    for (int i = 0; i < 4; i++) {
        int l = l0 + ts + i;
        float pos = ((float)l + 0.5f) * LSCALE - 0.5f;
        pos = fminf(fmaxf(pos, 0.f), (float)(TFRAMES - 1));
        int i0 = (int)pos;
        int i1 = min(i0 + 1, TFRAMES - 1);
        w[i] = pos - (float)i0;
        fA[i] = i0 - f0;
        fB[i] = i1 - f0;
    }

    float acc0[4] = {0.f, 0.f, 0.f, 0.f};
    float acc1[4] = {0.f, 0.f, 0.f, 0.f};
    float xw[8];
    {
        float4 xa = *(const float4*)&sx[ts];
        float4 xb = *(const float4*)&sx[ts + 4];
        xw[0] = xa.x; xw[1] = xa.y; xw[2] = xa.z; xw[3] = xa.w;
        xw[4] = xb.x; xw[5] = xb.y; xw[6] = xb.z; xw[7] = xb.w;
    }
    if (fA[0] == fA[3]) {
        const float* rA = sNF[fA[0]];
        const float* rB = sNF[fB[0]];
#pragma unroll
        for (int c = 0; c < 16; c++) {
#pragma unroll
            for (int j = 0; j < 4; j++) {
                int k = c * 4 + j;
                float wa = rA[k], wb = rB[k];
#pragma unroll
                for (int i = 0; i < 4; i++) {
                    float xv = xw[j + i];
                    acc0[i] += xv * wa;
                    acc1[i] += xv * wb;
                }
            }
            if (c < 15) {
#pragma unroll
                for (int i = 0; i < 4; i++) xw[i] = xw[i + 4];
                float4 xn = *(const float4*)&sx[ts + c * 4 + 8];
                xw[4] = xn.x; xw[5] = xn.y; xw[6] = xn.z; xw[7] = xn.w;
            }
        }
    } else {
#pragma unroll 4
        for (int c = 0; c < 16; c++) {
#pragma unroll
            for (int j = 0; j < 4; j++) {
                int k = c * 4 + j;
#pragma unroll
                for (int i = 0; i < 4; i++) {
                    float xv = xw[j + i];
                    acc0[i] += xv * sNF[fA[i]][k];
                    acc1[i] += xv * sNF[fB[i]][k];
                }
            }
            if (c < 15) {
#pragma unroll
                for (int i = 0; i < 4; i++) xw[i] = xw[i + 4];
                float4 xn = *(const float4*)&sx[ts + c * 4 + 8];
                xw[4] = xn.x; xw[5] = xn.y; xw[6] = xn.z; xw[7] = xn.w;
            }
        }
    }
    float res[4];
#pragma unroll
    for (int i = 0; i < 4; i++) res[i] = acc0[i] * (1.f - w[i]) + acc1[i] * w[i];
    *(float4*)&filt[(size_t)b * LSAMP + l0 + ts] = make_float4(res[0], res[1], res[2], res[3]);
}

// ---------------- filter bank via blended WF + gate + outputs (l-chunked) ----------------
#define STILE 512
__global__ void __launch_bounds__(128) shape_out3(const float* __restrict__ filt,
                                                  const float* __restrict__ wf,
                                                  const float* __restrict__ attf,
                                                  const float* __restrict__ intf,
                                                  float* __restrict__ out, int write_gate,
                                                  int xoff) {
    __shared__ float sWF[6][32];
    __shared__ __align__(16) float sx[STILE + 40];
    __shared__ float sgr[STILE + 4];
    __shared__ float sia[16];
    const int b = blockIdx.y;
    const int l0 = (blockIdx.x + xoff) * STILE;
    const int tid = threadIdx.x;
    const int f0 = max(0, (int)floorf((l0 + 0.5f) * LSCALE - 0.5f));

    for (int i = tid; i < 6 * 32; i += 128) {
        int row = i >> 5, k = i & 31;
        sWF[row][k] = wf[((size_t)b * TFRAMES + min(f0 + row, TFRAMES - 1)) * 32 + k];
    }
    for (int i = tid; i < STILE + 40; i += 128) {
        int l = l0 + i - 15;
        sx[i] = (l >= 0 && l < LSAMP) ? filt[(size_t)b * LSAMP + l] : 0.f;
    }
    const int fg0 = max(0, (int)floorf((l0 - 2.5f) * LSCALE - 0.5f));
    if (tid < 16) {
        int fi = tid & 7;
        int fr = min(fg0 + fi, TFRAMES - 1);
        sia[tid] = (tid < 8) ? intf[b * TFRAMES + fr] : attf[b * TFRAMES + fr];
    }
    __syncthreads();

    for (int i = tid; i < STILE + 4; i += 128) {
        int j = l0 + i - 2;
        if (j < 0) j = -j;
        if (j > LSAMP - 1) j = 2 * (LSAMP - 1) - j;
        float il = lin1s(sia, j, fg0);
        float diff = (j == 0) ? 0.f : (il - lin1s(sia, j - 1, fg0));
        float gv = il;
        if (diff > 0.f) {
            float e = il;
            if (diff > 0.1f) e += lin1s(&sia[8], j, fg0) * 0.3f;
            gv = fminf(fmaxf(e, 0.f), 1.f);
        }
        sgr[i] = gv;
    }
    __syncthreads();

    const int ts = tid * 4;
    int fA[4], fB[4];
    float w[4];
#pragma unroll
    for (int i = 0; i < 4; i++) {
        int l = l0 + ts + i;
        float pos = ((float)l + 0.5f) * LSCALE - 0.5f;
        pos = fminf(fmaxf(pos, 0.f), (float)(TFRAMES - 1));
        int i0 = (int)pos;
        int i1 = min(i0 + 1, TFRAMES - 1);
        w[i] = pos - (float)i0;
        fA[i] = i0 - f0;
        fB[i] = i1 - f0;
    }

    float acc0[4] = {0.f, 0.f, 0.f, 0.f};
    float acc1[4] = {0.f, 0.f, 0.f, 0.f};
    float xw[8];
    {
        float4 xa = *(const float4*)&sx[ts];
        float4 xb = *(const float4*)&sx[ts + 4];
        xw[0] = xa.x; xw[1] = xa.y; xw[2] = xa.z; xw[3] = xa.w;
        xw[4] = xb.x; xw[5] = xb.y; xw[6] = xb.z; xw[7] = xb.w;
    }
    if (fA[0] == fA[3]) {
        const float* rA = sWF[fA[0]];
        const float* rB = sWF[fB[0]];
#pragma unroll
        for (int c = 0; c < 8; c++) {
#pragma unroll
            for (int j = 0; j < 4; j++) {
                int k = c * 4 + j;
                float wa = rA[k], wb = rB[k];
#pragma unroll
                for (int i = 0; i < 4; i++) {
                    float xv = xw[j + i];
                    acc0[i] += xv * wa;
                    acc1[i] += xv * wb;
                }
            }
            if (c < 7) {
#pragma unroll
                for (int i = 0; i < 4; i++) xw[i] = xw[i + 4];
                float4 xn = *(const float4*)&sx[ts + c * 4 + 8];
                xw[4] = xn.x; xw[5] = xn.y; xw[6] = xn.z; xw[7] = xn.w;
            }
        }
    } else {
#pragma unroll 4
        for (int c = 0; c < 8; c++) {
#pragma unroll
            for (int j = 0; j < 4; j++) {
                int k = c * 4 + j;
#pragma unroll
                for (int i = 0; i < 4; i++) {
                    float xv = xw[j + i];
                    acc0[i] += xv * sWF[fA[i]][k];
                    acc1[i] += xv * sWF[fB[i]][k];
                }
            }
            if (c < 7) {
#pragma unroll
                for (int i = 0; i < 4; i++) xw[i] = xw[i + 4];
                float4 xn = *(const float4*)&sx[ts + c * 4 + 8];
                xw[4] = xn.x; xw[5] = xn.y; xw[6] = xn.z; xw[7] = xn.w;
            }
        }
    }

    float shaped[4];
#pragma unroll
    for (int i = 0; i < 4; i++) shaped[i] = acc0[i] * (1.f - w[i]) + acc1[i] * w[i];

    float s[8];
#pragma unroll
    for (int ii = 0; ii < 8; ii++) s[ii] = sgr[ts + ii];
    float gv0 = 0.2f * (s[0] + s[1] + s[2] + s[3] + s[4]);
    float gv1 = 0.2f * (s[1] + s[2] + s[3] + s[4] + s[5]);
    float gv2 = 0.2f * (s[2] + s[3] + s[4] + s[5] + s[6]);
    float gv3 = 0.2f * (s[3] + s[4] + s[5] + s[6] + s[7]);
    *(float4*)&out[(size_t)b * LSAMP + l0 + ts] =
        make_float4(shaped[0] * gv0, shaped[1] * gv1, shaped[2] * gv2, shaped[3] * gv3);
    if (write_gate)
        *(float4*)&out[(size_t)BATCH * LSAMP + (size_t)b * LSAMP + l0 + ts] =
            make_float4(gv0, gv1, gv2, gv3);
}

// ---------------- launch ----------------
#define SHP_A 168

extern "C" void kernel_launch(void* const* d_in, const int* in_sizes, int n_in,
                              void* d_out, int out_size) {
    const float* cond  = (const float*)d_in[0];
    const float* wn    = (const float*)d_in[1];
    const float* np_w1 = (const float*)d_in[2];
    const float* np_b1 = (const float*)d_in[3];
    const float* np_w2 = (const float*)d_in[4];
    const float* np_b2 = (const float*)d_in[5];
    const float* np_w3 = (const float*)d_in[6];
    const float* np_b3 = (const float*)d_in[7];
    const float* ss_w1 = (const float*)d_in[8];
    const float* ss_b1 = (const float*)d_in[9];
    const float* ss_w2 = (const float*)d_in[10];
    const float* ss_b2 = (const float*)d_in[11];
    const float* fb_w  = (const float*)d_in[12];
    const float* nt_w  = (const float*)d_in[13];
    float* out = (float*)d_out;

    void *p_h1, *p_pA, *p_pB, *p_att, *p_int, *p_ssg, *p_wf, *p_nf, *p_filt;
    void *p_wt1, *p_wt2, *p_wts, *p_w3t, *p_w2t;
    cudaGetSymbolAddress(&p_h1, g_h1);
    cudaGetSymbolAddress(&p_pA, g_partA);
    cudaGetSymbolAddress(&p_pB, g_partB);
    cudaGetSymbolAddress(&p_att, g_att);
    cudaGetSymbolAddress(&p_int, g_int);
    cudaGetSymbolAddress(&p_ssg, g_ssg);
    cudaGetSymbolAddress(&p_wf, g_wf);
    cudaGetSymbolAddress(&p_nf, g_nf);
    cudaGetSymbolAddress(&p_filt, g_filt);
    cudaGetSymbolAddress(&p_wt1, g_wt1);
    cudaGetSymbolAddress(&p_wt2, g_wt2);
    cudaGetSymbolAddress(&p_wts, g_wts);
    cudaGetSymbolAddress(&p_w3t, g_w3t);
    cudaGetSymbolAddress(&p_w2t, g_w2t);

    static cudaStream_t s2 = nullptr, s3 = nullptr;
    static cudaEvent_t ev_fork = nullptr, ev_w1 = nullptr, ev_rest = nullptr,
                       ev_join = nullptr, ev_cbA = nullptr, ev_done3 = nullptr;
    if (s2 == nullptr) {
        cudaStreamCreateWithFlags(&s2, cudaStreamNonBlocking);
        cudaStreamCreateWithFlags(&s3, cudaStreamNonBlocking);
        cudaEventCreateWithFlags(&ev_fork, cudaEventDisableTiming);
        cudaEventCreateWithFlags(&ev_w1, cudaEventDisableTiming);
        cudaEventCreateWithFlags(&ev_rest, cudaEventDisableTiming);
        cudaEventCreateWithFlags(&ev_join, cudaEventDisableTiming);
        cudaEventCreateWithFlags(&ev_cbA, cudaEventDisableTiming);
        cudaEventCreateWithFlags(&ev_done3, cudaEventDisableTiming);
    }

    int write_gate = (out_size >= 2 * BATCH * LSAMP) ? 1 : 0;

    cudaEventRecord(ev_fork, 0);
    cudaStreamWaitEvent(s2, ev_fork, 0);
    cudaStreamWaitEvent(s3, ev_fork, 0);

    prep_w1<<<96, 256>>>(np_w1, (float*)p_wt1);
    cudaEventRecord(ev_w1, 0);
    prep_rest<<<212, 256, 0, s2>>>(np_w2, ss_w1, np_w3, ss_w2,
                                   (float*)p_wt2, (float*)p_wts, (float*)p_w3t, (float*)p_w2t);
    cudaEventRecord(ev_rest, s2);

    // side branch (s2)
    conv3t<128, 128><<<dim3(13, 2, BATCH), 256, 0, s2>>>(cond, (const float*)p_wts, ss_b1,
                                                          (float*)p_ssg);
    ss_head4<<<dim3(13, BATCH), 256, 0, s2>>>((const float*)p_ssg, (const float*)p_w2t,
                                              ss_b2, nt_w, (float*)p_nf);
    mix_noise3<<<dim3(LSAMP / MTILE, BATCH), 128, 0, s2>>>(wn, (const float*)p_nf,
                                                           (float*)p_filt);
    cudaEventRecord(ev_join, s2);

    // main chunk A (s0)
    conv3s<128, 256><<<dim3(7, 8, BATCH), 256>>>(cond, (const float*)p_wt1, (float*)p_pA, 0);
    combine_range<<<(BATCH * 256 * (448 / 4) + 255) / 256, 256>>>(
        (const float*)p_pA, np_b1, (float*)p_h1, 0, 448);
    cudaEventRecord(ev_cbA, 0);
    cudaStreamWaitEvent(0, ev_rest, 0);
    conv3s<256, 256><<<dim3(6, 8, BATCH), 256>>>((const float*)p_h1, (const float*)p_wt2,
                                                 (float*)p_pB, 0);
    np_head5<<<dim3(6, BATCH), 256>>>((const float*)p_pB, np_b2, (const float*)p_w3t, np_b3,
                                      fb_w, (float*)p_wf, (float*)p_att, (float*)p_int, 0);
    cudaStreamWaitEvent(0, ev_join, 0);
    shape_out3<<<dim3(SHP_A, BATCH), 128>>>((const float*)p_filt, (const float*)p_wf,
                                            (const float*)p_att, (const float*)p_int,
                                            out, write_gate, 0);

    // main chunk B (s3)
    cudaStreamWaitEvent(s3, ev_w1, 0);
    conv3s<128, 256><<<dim3(6, 8, BATCH), 256, 0, s3>>>(cond, (const float*)p_wt1,
                                                        (float*)p_pA, 7);
    combine_range<<<(BATCH * 256 * (352 / 4) + 255) / 256, 256, 0, s3>>>(
        (const float*)p_pA, np_b1, (float*)p_h1, 448, 352);
    cudaStreamWaitEvent(s3, ev_cbA, 0);
    cudaStreamWaitEvent(s3, ev_rest, 0);
    conv3s<256, 256><<<dim3(7, 8, BATCH), 256, 0, s3>>>((const float*)p_h1,
                                                        (const float*)p_wt2, (float*)p_pB, 6);
    np_head5<<<dim3(7, BATCH), 256, 0, s3>>>((const float*)p_pB, np_b2, (const float*)p_w3t,
                                             np_b3, fb_w, (float*)p_wf, (float*)p_att,
                                             (float*)p_int, 6);
    cudaStreamWaitEvent(s3, ev_join, 0);
    shape_out3<<<dim3(LSAMP / STILE - SHP_A, BATCH), 128, 0, s3>>>(
        (const float*)p_filt, (const float*)p_wf, (const float*)p_att, (const float*)p_int,
        out, write_gate, SHP_A);
    cudaEventRecord(ev_done3, s3);

    cudaStreamWaitEvent(0, ev_done3, 0);
}